// round 1
// baseline (speedup 1.0000x reference)
#include <cuda_runtime.h>
#include <math.h>

static constexpr int BB = 64;
static constexpr int LL = 2048;
static constexpr int HH = 256;
static constexpr int VV = 32000;
static constexpr int TT = LL - 1;      // 2047 scan steps
static constexpr float BETA = 0.9f;
static constexpr float OMB  = 0.1f;    // 1 - beta
static constexpr int CH = 32;          // scan chunk length

// ---------------- scratch (device globals; no runtime allocation) ----------------
__device__ float g_e [(size_t)BB*LL*HH];        // gathered embeddings   134 MB
__device__ float g_ff[(size_t)BB*LL*2*HH];      // relu(e@W1+b1)         268 MB
__device__ float g_h [(size_t)BB*LL*HH];        // x then LayerNorm(h)   134 MB
__device__ float g_M [(size_t)BB*HH*HH];        // final fast-weight M    16.8 MB
__device__ float g_y [BB*HH];
__device__ float g_y2[BB*HH];

// ---------------- 1. embedding gather ----------------
__global__ void k_gather(const int* __restrict__ seq, const float* __restrict__ embed) {
    size_t idx = (size_t)blockIdx.x * blockDim.x + threadIdx.x;   // over B*L*64 float4
    int token = (int)(idx >> 6);
    int q     = (int)(idx & 63);
    int tok = seq[token];
    ((float4*)g_e)[idx] = ((const float4*)embed)[(size_t)tok * 64 + q];
}

// ---------------- 2. SGEMM 128x128x8, 8x8 per thread ----------------
// EPI=0: C = relu(A@B + bias)         (FFN layer 1)
// EPI=1: C = A@B + bias + E           (FFN layer 2 + residual)
template<int EPI>
__global__ __launch_bounds__(256) void k_sgemm(
    const float* __restrict__ A, const float* __restrict__ Bm,
    const float* __restrict__ bias, const float* __restrict__ E,
    float* __restrict__ C, int N, int K)
{
    __shared__ float As[8 * 128];   // transposed A tile
    __shared__ float Bs[8 * 128];
    int tid = threadIdx.x;
    int bx = blockIdx.x, by = blockIdx.y;
    const float* Ab = A  + (size_t)by * 128 * K;
    const float* Bb = Bm + bx * 128;

    int arow = tid >> 1;            // 0..127
    int acol = (tid & 1) * 4;       // 0 or 4
    int brow = tid >> 5;            // 0..7
    int bcol = (tid & 31) * 4;      // 0..124
    int tr = (tid >> 4) * 8;
    int tc = (tid & 15) * 8;

    float acc[8][8];
    #pragma unroll
    for (int m = 0; m < 8; ++m)
        #pragma unroll
        for (int n = 0; n < 8; ++n) acc[m][n] = 0.f;

    for (int k0 = 0; k0 < K; k0 += 8) {
        float4 a4 = *(const float4*)(Ab + (size_t)arow * K + k0 + acol);
        As[(acol+0)*128 + arow] = a4.x;
        As[(acol+1)*128 + arow] = a4.y;
        As[(acol+2)*128 + arow] = a4.z;
        As[(acol+3)*128 + arow] = a4.w;
        *(float4*)(Bs + brow*128 + bcol) = *(const float4*)(Bb + (size_t)(k0+brow) * N + bcol);
        __syncthreads();
        #pragma unroll
        for (int kk = 0; kk < 8; ++kk) {
            float4 ra0 = *(const float4*)(As + kk*128 + tr);
            float4 ra1 = *(const float4*)(As + kk*128 + tr + 4);
            float4 rb0 = *(const float4*)(Bs + kk*128 + tc);
            float4 rb1 = *(const float4*)(Bs + kk*128 + tc + 4);
            float ra[8] = {ra0.x, ra0.y, ra0.z, ra0.w, ra1.x, ra1.y, ra1.z, ra1.w};
            float rb[8] = {rb0.x, rb0.y, rb0.z, rb0.w, rb1.x, rb1.y, rb1.z, rb1.w};
            #pragma unroll
            for (int m = 0; m < 8; ++m)
                #pragma unroll
                for (int n = 0; n < 8; ++n) acc[m][n] += ra[m] * rb[n];
        }
        __syncthreads();
    }

    #pragma unroll
    for (int m = 0; m < 8; ++m) {
        size_t row = (size_t)by * 128 + tr + m;
        #pragma unroll
        for (int n = 0; n < 8; n += 4) {
            int col = bx * 128 + tc + n;
            float4 bia = *(const float4*)(bias + col);
            float4 v;
            v.x = acc[m][n+0] + bia.x;
            v.y = acc[m][n+1] + bia.y;
            v.z = acc[m][n+2] + bia.z;
            v.w = acc[m][n+3] + bia.w;
            if (EPI == 0) {
                v.x = fmaxf(v.x, 0.f); v.y = fmaxf(v.y, 0.f);
                v.z = fmaxf(v.z, 0.f); v.w = fmaxf(v.w, 0.f);
            } else {
                float4 e4 = *(const float4*)(E + row * N + col);
                v.x += e4.x; v.y += e4.y; v.z += e4.z; v.w += e4.w;
            }
            *(float4*)(C + row * N + col) = v;
        }
    }
}

// ---------------- 3. LayerNorm (in place on g_h), one row per block ----------------
__global__ void k_ln(const float* __restrict__ gamma, const float* __restrict__ beta_ln) {
    size_t row = blockIdx.x;
    int tid = threadIdx.x;
    float* xp = g_h + row * HH;
    float x = xp[tid];
    __shared__ float red[8];
    float s = x;
    #pragma unroll
    for (int o = 16; o; o >>= 1) s += __shfl_xor_sync(0xffffffffu, s, o);
    if ((tid & 31) == 0) red[tid >> 5] = s;
    __syncthreads();
    float mu = 0.f;
    #pragma unroll
    for (int i = 0; i < 8; ++i) mu += red[i];
    mu *= (1.0f / HH);
    __syncthreads();
    float d = x - mu;
    float v = d * d;
    #pragma unroll
    for (int o = 16; o; o >>= 1) v += __shfl_xor_sync(0xffffffffu, v, o);
    if ((tid & 31) == 0) red[tid >> 5] = v;
    __syncthreads();
    float var = 0.f;
    #pragma unroll
    for (int i = 0; i < 8; ++i) var += red[i];
    var *= (1.0f / HH);
    xp[tid] = d * rsqrtf(var + 1e-5f) * gamma[tid] + beta_ln[tid];
}

// ---------------- 4. chunked momentum delta-rule scan ----------------
// CTA (b, half): owns M rows [r0, r0+128) of batch b, M resident in smem.
// Per chunk:  G/coefs -> U = K M^T -> forward substitution (componentwise!) -> rank-C M update.
static constexpr int SCAN_SMEM_FLOATS = 128*257 + CH*257 + CH*128 + CH*CH + CH + 40;
static constexpr int SCAN_SMEM_BYTES  = SCAN_SMEM_FLOATS * 4;   // 185,248 B

__global__ __launch_bounds__(256, 1) void k_scan() {
    extern __shared__ float sm[];
    float* sM  = sm;                       // [128][257]  M rows (pad 257: bank = (i+j)%32)
    float* sK  = sM + 128*257;             // [CH][257]   k chunk, all 256 comps
    float* sD  = sK + CH*257;              // [CH][128]   rhs then d (own components)
    float* sA  = sD + CH*128;              // [CH][CH]    coupling coefs
    float* sc  = sA + CH*CH;               // [CH]        1/(||k||^2+eps)
    float* spw = sc + CH;                  // [CH+1]      beta powers

    int tid = threadIdx.x;
    int b   = blockIdx.x >> 1;
    int r0  = (blockIdx.x & 1) * 128;

    for (int i = tid; i < 128*257; i += 256) sM[i] = 0.f;
    if (tid == 0) {
        spw[0] = 1.f;
        for (int i = 1; i <= CH; ++i) spw[i] = spw[i-1] * BETA;
    }
    __syncthreads();

    // U-phase mapping: conflict-free by construction with 257 stride
    const int u_ig = tid >> 3;       // i0 = 4*u_ig  (0..124)
    const int u_tg = tid & 7;        // lt0 = 4*u_tg (0..28)
    // update-phase mapping
    const int m_ig = tid & 15;       // i0 = 8*m_ig
    const int m_jg = tid >> 4;       // j0 = 16*m_jg

    const float* hb = g_h + (size_t)b * LL * HH;

    for (int t0 = 0; t0 < TT; t0 += CH) {
        int Cc = min(CH, TT - t0);
        __syncthreads();   // everyone done with previous chunk's sK/sD/sM reads

        // ---- load K chunk (float4 loads, scalar swizzled stores) ----
        for (int idx = tid; idx < Cc * 64; idx += 256) {
            int lt = idx >> 6, q = idx & 63;
            float4 v = *(const float4*)(hb + (size_t)(t0 + lt) * HH + q * 4);
            float* dst = sK + lt*257 + q*4;
            dst[0] = v.x; dst[1] = v.y; dst[2] = v.z; dst[3] = v.w;
        }
        __syncthreads();

        // ---- Gram matrix + norms ----
        int P = Cc * (Cc + 1) / 2;
        for (int p = tid; p < P; p += 256) {
            int t = (int)((sqrtf(8.f * p + 1.f) - 1.f) * 0.5f);
            while ((t + 1) * (t + 2) / 2 <= p) ++t;
            while (t * (t + 1) / 2 > p) --t;
            int s = p - t * (t + 1) / 2;
            const float* kt = sK + t*257;
            const float* ks = sK + s*257;
            float dot = 0.f;
            #pragma unroll 8
            for (int j = 0; j < HH; ++j) dot += kt[j] * ks[j];
            if (s == t) sc[t] = dot;
            else        sA[t*CH + s] = dot;
        }
        __syncthreads();
        if (tid < Cc) sc[tid] = 1.0f / (sc[tid] + 1e-6f);
        __syncthreads();
        for (int p = tid; p < P; p += 256) {
            int t = (int)((sqrtf(8.f * p + 1.f) - 1.f) * 0.5f);
            while ((t + 1) * (t + 2) / 2 <= p) ++t;
            while (t * (t + 1) / 2 > p) --t;
            int s = p - t * (t + 1) / 2;
            if (s < t) sA[t*CH + s] *= sc[t] * OMB * spw[t - 1 - s];
        }
        __syncthreads();

        // ---- U = K * M_rows^T  (register GEMM), fold into rhs -> sD ----
        {
            int i0 = u_ig * 4, lt0 = u_tg * 4;
            float acc[4][4];
            #pragma unroll
            for (int r = 0; r < 4; ++r)
                #pragma unroll
                for (int c = 0; c < 4; ++c) acc[r][c] = 0.f;
            #pragma unroll 4
            for (int j = 0; j < HH; ++j) {
                float a0 = sM[(i0+0)*257 + j], a1 = sM[(i0+1)*257 + j];
                float a2 = sM[(i0+2)*257 + j], a3 = sM[(i0+3)*257 + j];
                float b0 = sK[(lt0+0)*257 + j], b1 = sK[(lt0+1)*257 + j];
                float b2 = sK[(lt0+2)*257 + j], b3 = sK[(lt0+3)*257 + j];
                acc[0][0] += a0*b0; acc[0][1] += a0*b1; acc[0][2] += a0*b2; acc[0][3] += a0*b3;
                acc[1][0] += a1*b0; acc[1][1] += a1*b1; acc[1][2] += a1*b2; acc[1][3] += a1*b3;
                acc[2][0] += a2*b0; acc[2][1] += a2*b1; acc[2][2] += a2*b2; acc[2][3] += a2*b3;
                acc[3][0] += a3*b0; acc[3][1] += a3*b1; acc[3][2] += a3*b2; acc[3][3] += a3*b3;
            }
            #pragma unroll
            for (int c = 0; c < 4; ++c) {
                int lt = lt0 + c;
                if (lt < Cc) {
                    float coef = sc[lt] * spw[lt];
                    #pragma unroll
                    for (int r = 0; r < 4; ++r) {
                        int i = i0 + r;
                        sD[lt*128 + i] = sK[lt*257 + r0 + i] - coef * acc[r][c];
                    }
                }
            }
        }
        __syncthreads();

        // ---- forward substitution (componentwise in i) ----
        {
            int i  = tid & 127;
            int tg = tid >> 7;
            for (int s = 0; s < Cc - 1; ++s) {
                __syncthreads();
                float ds = sD[s*128 + i];
                for (int t = s + 1 + tg; t < Cc; t += 2)
                    sD[t*128 + i] -= sA[t*CH + s] * ds;
            }
            __syncthreads();
        }

        // ---- rank-Cc M update:  M = beta^Cc * M + sum_s w_s d_s k_s^T ----
        {
            float bc = spw[Cc];
            int i0 = m_ig * 8, j0 = m_jg * 16;
            float acc[8][16];
            #pragma unroll
            for (int r = 0; r < 8; ++r)
                #pragma unroll
                for (int c = 0; c < 16; ++c)
                    acc[r][c] = sM[(i0+r)*257 + j0 + c] * bc;
            for (int s = 0; s < Cc; ++s) {
                float w = OMB * spw[Cc - 1 - s];
                float4 d0 = *(const float4*)(sD + s*128 + i0);
                float4 d1 = *(const float4*)(sD + s*128 + i0 + 4);
                float dr[8] = {d0.x*w, d0.y*w, d0.z*w, d0.w*w,
                               d1.x*w, d1.y*w, d1.z*w, d1.w*w};
                #pragma unroll
                for (int c = 0; c < 16; ++c) {
                    float kv = sK[s*257 + j0 + c];
                    #pragma unroll
                    for (int r = 0; r < 8; ++r) acc[r][c] += dr[r] * kv;
                }
            }
            #pragma unroll
            for (int r = 0; r < 8; ++r)
                #pragma unroll
                for (int c = 0; c < 16; ++c)
                    sM[(i0+r)*257 + j0 + c] = acc[r][c];
        }
    }

    __syncthreads();
    for (int idx = tid; idx < 128 * HH; idx += 256) {
        int i = idx >> 8, j = idx & 255;
        g_M[((size_t)b * HH + r0 + i) * HH + j] = sM[i*257 + j];
    }
}

// ---------------- 5. readout: y = M h_last ----------------
__global__ void k_read1() {
    int b = blockIdx.x;
    int tid = threadIdx.x;
    __shared__ float hl[HH];
    hl[tid] = g_h[((size_t)b * LL + (LL - 1)) * HH + tid];
    __syncthreads();
    int w = tid >> 5, lane = tid & 31;
    for (int i = w; i < HH; i += 8) {
        const float* Mr = g_M + ((size_t)b * HH + i) * HH;
        float s = 0.f;
        #pragma unroll
        for (int j = lane; j < HH; j += 32) s += Mr[j] * hl[j];
        #pragma unroll
        for (int o = 16; o; o >>= 1) s += __shfl_xor_sync(0xffffffffu, s, o);
        if (lane == 0) g_y[b * HH + i] = s;
    }
}

// ---------------- 6. y2 = y @ rp_W + rp_b ----------------
__global__ void k_read2(const float* __restrict__ rp_W, const float* __restrict__ rp_b) {
    int b = blockIdx.x, n = threadIdx.x;
    __shared__ float ys[HH];
    ys[n] = g_y[b * HH + n];
    __syncthreads();
    float acc = rp_b[n];
    #pragma unroll 4
    for (int k = 0; k < HH; ++k) acc += ys[k] * rp_W[k * HH + n];
    g_y2[b * HH + n] = acc;
}

// ---------------- 7. out = y2 @ out_W + out_b, out_W tile staged in smem ----------------
static constexpr int OUT_SMEM_BYTES = (HH * 128 + BB * 257) * 4;   // 196,864 B

__global__ __launch_bounds__(256) void k_out(
    const float* __restrict__ out_W, const float* __restrict__ out_b,
    float* __restrict__ out)
{
    extern __shared__ float sm[];
    float* sW  = sm;               // [256 k][128 n]
    float* sy2 = sm + HH * 128;    // [64 b][257]
    int tid = threadIdx.x;
    int n_base = blockIdx.x * 128;

    for (int idx = tid; idx < HH * 32; idx += 256) {    // 8192 float4
        int k = idx >> 5, q = idx & 31;
        *(float4*)(sW + k*128 + q*4) = *(const float4*)(out_W + (size_t)k * VV + n_base + q*4);
    }
    for (int idx = tid; idx < BB * 64; idx += 256) {
        int bb = idx >> 6, q = idx & 63;
        float4 v = *(const float4*)(g_y2 + bb * HH + q*4);
        float* d = sy2 + bb*257 + q*4;
        d[0] = v.x; d[1] = v.y; d[2] = v.z; d[3] = v.w;
    }
    __syncthreads();

    int bg = tid >> 4, ng = tid & 15;
    int b0 = bg * 4, n0 = ng * 8;
    float acc[4][8];
    #pragma unroll
    for (int r = 0; r < 4; ++r)
        #pragma unroll
        for (int c = 0; c < 8; ++c) acc[r][c] = 0.f;
    for (int k = 0; k < HH; ++k) {
        float4 w0 = *(const float4*)(sW + k*128 + n0);
        float4 w1 = *(const float4*)(sW + k*128 + n0 + 4);
        float wv[8] = {w0.x, w0.y, w0.z, w0.w, w1.x, w1.y, w1.z, w1.w};
        #pragma unroll
        for (int r = 0; r < 4; ++r) {
            float yv = sy2[(b0+r)*257 + k];
            #pragma unroll
            for (int c = 0; c < 8; ++c) acc[r][c] += yv * wv[c];
        }
    }
    #pragma unroll
    for (int r = 0; r < 4; ++r)
        #pragma unroll
        for (int c = 0; c < 8; ++c)
            out[(size_t)(b0+r) * VV + n_base + n0 + c] = acc[r][c] + out_b[n_base + n0 + c];
}

// ---------------- launch ----------------
extern "C" void kernel_launch(void* const* d_in, const int* in_sizes, int n_in,
                              void* d_out, int out_size) {
    (void)in_sizes; (void)n_in; (void)out_size;
    const int*   seq     = (const int*)  d_in[0];
    const float* embed   = (const float*)d_in[1];
    const float* W1      = (const float*)d_in[2];
    const float* b1      = (const float*)d_in[3];
    const float* W2      = (const float*)d_in[4];
    const float* b2      = (const float*)d_in[5];
    const float* gamma   = (const float*)d_in[6];
    const float* beta_ln = (const float*)d_in[7];
    const float* rp_W    = (const float*)d_in[8];
    const float* rp_b    = (const float*)d_in[9];
    const float* out_W   = (const float*)d_in[10];
    const float* out_b   = (const float*)d_in[11];
    float* out = (float*)d_out;

    float *pe, *pff, *ph;
    cudaGetSymbolAddress((void**)&pe,  g_e);
    cudaGetSymbolAddress((void**)&pff, g_ff);
    cudaGetSymbolAddress((void**)&ph,  g_h);

    cudaFuncSetAttribute(k_scan, cudaFuncAttributeMaxDynamicSharedMemorySize, SCAN_SMEM_BYTES);
    cudaFuncSetAttribute(k_out,  cudaFuncAttributeMaxDynamicSharedMemorySize, OUT_SMEM_BYTES);

    // 1. gather
    k_gather<<<(BB * LL * 64) / 256, 256>>>(seq, embed);
    // 2. ff1 = relu(e@W1 + b1)
    k_sgemm<0><<<dim3(2*HH/128, BB*LL/128), 256>>>(pe, W1, b1, nullptr, pff, 2*HH, HH);
    // 3. x = ff1@W2 + b2 + e   (into g_h)
    k_sgemm<1><<<dim3(HH/128, BB*LL/128), 256>>>(pff, W2, b2, pe, ph, HH, 2*HH);
    // 4. h = LayerNorm(x) in place
    k_ln<<<BB * LL, HH>>>(gamma, beta_ln);
    // 5. chunked delta-rule scan (2 CTAs per batch, M smem-resident)
    k_scan<<<BB * 2, 256, SCAN_SMEM_BYTES>>>();
    // 6. readout
    k_read1<<<BB, 256>>>();
    k_read2<<<BB, HH>>>(rp_W, rp_b);
    k_out<<<VV / 128, 256, OUT_SMEM_BYTES>>>(out_W, out_b, out);
}

// round 3
// speedup vs baseline: 1.1386x; 1.1386x over previous
#include <cuda_runtime.h>
#include <cuda_bf16.h>
#include <math.h>
#include <stdint.h>

static constexpr int BB = 64;
static constexpr int LL = 2048;
static constexpr int HH = 256;
static constexpr int VV = 32000;
static constexpr int TT = LL - 1;
static constexpr float BETA = 0.9f;
static constexpr float OMB  = 0.1f;
static constexpr int CH = 32;

// ---------------- scratch (device globals) ----------------
__device__ float g_h [(size_t)BB*LL*HH];               // x then LayerNorm(h)
__device__ __nv_bfloat16 g_ffh[(size_t)BB*LL*2*HH];    // relu(e@W1+b1) hi
__device__ __nv_bfloat16 g_ffl[(size_t)BB*LL*2*HH];    // lo
__device__ __nv_bfloat16 g_w1h[512*256], g_w1l[512*256];   // W1^T [N=512][K=256]
__device__ __nv_bfloat16 g_w2h[256*512], g_w2l[256*512];   // W2^T [N=256][K=512]
__device__ float g_M [(size_t)BB*HH*HH];
__device__ float g_y [BB*HH];
__device__ float g_y2[BB*HH];

// ---------------- helpers ----------------
#define SWZ(o) ((o) ^ (((o) >> 3) & 0x70))

__device__ __forceinline__ uint32_t smem_u32(const void* p) {
    uint32_t a;
    asm("{ .reg .u64 t; cvta.to.shared.u64 t, %1; cvt.u32.u64 %0, t; }" : "=r"(a) : "l"(p));
    return a;
}
__device__ __forceinline__ uint32_t pack2(__nv_bfloat16 a, __nv_bfloat16 b) {
    __nv_bfloat162 t = __halves2bfloat162(a, b);
    return *reinterpret_cast<uint32_t*>(&t);
}
__device__ __forceinline__ void ldsm_x4(uint32_t* r, uint32_t addr) {
    asm volatile("ldmatrix.sync.aligned.m8n8.x4.shared.b16 {%0,%1,%2,%3}, [%4];"
        : "=r"(r[0]), "=r"(r[1]), "=r"(r[2]), "=r"(r[3]) : "r"(addr));
}
__device__ __forceinline__ void mma_bf16(float* d, const uint32_t* a, uint32_t b0, uint32_t b1) {
    asm volatile("mma.sync.aligned.m16n8k16.row.col.f32.bf16.bf16.f32 "
        "{%0,%1,%2,%3}, {%4,%5,%6,%7}, {%8,%9}, {%0,%1,%2,%3};"
        : "+f"(d[0]), "+f"(d[1]), "+f"(d[2]), "+f"(d[3])
        : "r"(a[0]), "r"(a[1]), "r"(a[2]), "r"(a[3]), "r"(b0), "r"(b1));
}

// ---------------- 0. weight transpose + bf16 split ----------------
__global__ void k_prep(const float* __restrict__ W1, const float* __restrict__ W2) {
    int idx = blockIdx.x * blockDim.x + threadIdx.x;   // 0 .. 131071
    {   // W1t [n=512][k=256] = W1[k][n]
        int n = idx >> 8, k = idx & 255;
        float w = W1[k * 512 + n];
        __nv_bfloat16 h = __float2bfloat16(w);
        g_w1h[idx] = h;
        g_w1l[idx] = __float2bfloat16(w - __bfloat162float(h));
    }
    {   // W2t [n=256][k=512] = W2[k][n]
        int n = idx >> 9, k = idx & 511;
        float w = W2[k * 256 + n];
        __nv_bfloat16 h = __float2bfloat16(w);
        g_w2h[idx] = h;
        g_w2l[idx] = __float2bfloat16(w - __bfloat162float(h));
    }
}

// ---------------- 1+2. FFN GEMMs on HMMA (mma.sync bf16, split-2) ----------------
// PHASE 1: ff = relu(gather(embed,seq) @ W1 + b1) -> g_ffh/g_ffl  (M=131072, N=512, K=256)
// PHASE 2: x  = ff @ W2 + b2 + gather(embed,seq)  -> g_h          (M=131072, N=256, K=512)
// CTA tile 128x128, 8 warps (2m x 4n), warp tile 64x32, K chunk 64 (SW128 smem).
static constexpr int FFN_SMEM = 1024 + 4 * 16384;   // 66560 B

template<int PHASE>
__global__ __launch_bounds__(256) void k_ffn(
    const int* __restrict__ seq, const float* __restrict__ embed,
    const float* __restrict__ bias)
{
    constexpr int K   = (PHASE == 1) ? HH : 2 * HH;
    constexpr int NC  = K / 64;
    constexpr int NG  = (PHASE == 1) ? 2 * HH : HH;   // output row stride

    extern __shared__ char sm[];
    int*   sseq  = (int*)sm;              // 128 ints
    float* sbias = (float*)(sm + 512);    // 128 floats
    char* A_HI = sm + 1024;
    char* A_LO = A_HI + 16384;
    char* B_HI = A_LO + 16384;
    char* B_LO = B_HI + 16384;
    const uint32_t aHI = smem_u32(A_HI), aLO = smem_u32(A_LO);
    const uint32_t bHI = smem_u32(B_HI), bLO = smem_u32(B_LO);

    const int tid = threadIdx.x, wid = tid >> 5, lid = tid & 31;
    const int wm = wid & 1, wn = wid >> 1;            // warp 2x4
    const int m0  = blockIdx.y * 128;
    const int nb0 = blockIdx.x * 128;

    if (tid < 128) {
        sseq[tid]  = seq[m0 + tid];
        sbias[tid] = bias[nb0 + tid];
    }

    float acc[4][4][4];   // [mf][n8 frag][4]
    #pragma unroll
    for (int a = 0; a < 4; ++a)
        #pragma unroll
        for (int b = 0; b < 4; ++b)
            #pragma unroll
            for (int c = 0; c < 4; ++c) acc[a][b][c] = 0.f;

    const int r = tid >> 1, half = tid & 1;

    for (int c = 0; c < NC; ++c) {
        int k0 = c * 64;
        __syncthreads();   // previous chunk's ldmatrix reads done

        // ---- A chunk: 128 rows x 64 bf16, hi/lo, SW128 ----
        if (PHASE == 1) {
            int tok = sseq[r];
            const float* src = embed + (size_t)tok * HH + k0 + half * 32;
            #pragma unroll
            for (int j = 0; j < 4; ++j) {
                float4 v0 = *(const float4*)(src + j * 8);
                float4 v1 = *(const float4*)(src + j * 8 + 4);
                float f[8] = {v0.x, v0.y, v0.z, v0.w, v1.x, v1.y, v1.z, v1.w};
                uint32_t hw[4], lw[4];
                #pragma unroll
                for (int q = 0; q < 4; ++q) {
                    __nv_bfloat16 h0 = __float2bfloat16(f[2*q]);
                    __nv_bfloat16 h1 = __float2bfloat16(f[2*q+1]);
                    hw[q] = pack2(h0, h1);
                    lw[q] = pack2(__float2bfloat16(f[2*q]   - __bfloat162float(h0)),
                                  __float2bfloat16(f[2*q+1] - __bfloat162float(h1)));
                }
                uint32_t off = SWZ((uint32_t)(r * 128 + half * 64 + j * 16));
                *(uint4*)(A_HI + off) = make_uint4(hw[0], hw[1], hw[2], hw[3]);
                *(uint4*)(A_LO + off) = make_uint4(lw[0], lw[1], lw[2], lw[3]);
            }
        } else {
            const uint4* sh = (const uint4*)(g_ffh + (size_t)(m0 + r) * 512 + k0 + half * 32);
            const uint4* sl = (const uint4*)(g_ffl + (size_t)(m0 + r) * 512 + k0 + half * 32);
            #pragma unroll
            for (int j = 0; j < 4; ++j) {
                uint32_t off = SWZ((uint32_t)(r * 128 + half * 64 + j * 16));
                *(uint4*)(A_HI + off) = sh[j];
                *(uint4*)(A_LO + off) = sl[j];
            }
        }
        // ---- B chunk: 128 rows (n) x 64 bf16 ----
        {
            int rr = tid & 127, sel = tid >> 7;
            const __nv_bfloat16* w =
                (PHASE == 1) ? (sel ? g_w1l : g_w1h) : (sel ? g_w2l : g_w2h);
            char* dst = sel ? B_LO : B_HI;
            const uint4* srcp = (const uint4*)(w + (size_t)(nb0 + rr) * K + k0);
            #pragma unroll
            for (int j = 0; j < 8; ++j)
                *(uint4*)(dst + SWZ((uint32_t)(rr * 128 + j * 16))) = srcp[j];
        }
        __syncthreads();

        // ---- compute: 4 k-steps of 16 ----
        #pragma unroll
        for (int ks = 0; ks < 4; ++ks) {
            uint32_t colA = ks * 32 + ((lid >> 4) << 4);
            uint32_t ah[4][4];
            #pragma unroll
            for (int mf = 0; mf < 4; ++mf) {
                uint32_t row = wm * 64 + mf * 16 + (lid & 15);
                uint32_t off = SWZ(row * 128 + colA);
                ldsm_x4(ah[mf], aHI + off);
            }
            uint32_t bh[2][4], bl[2][4];
            #pragma unroll
            for (int nf = 0; nf < 2; ++nf) {
                uint32_t row = wn * 32 + nf * 16 + ((lid >> 4) << 3) + (lid & 7);
                uint32_t colB = ks * 32 + (((lid >> 3) & 1) << 4);
                uint32_t off = SWZ(row * 128 + colB);
                ldsm_x4(bh[nf], bHI + off);
                ldsm_x4(bl[nf], bLO + off);
            }
            // hi*hi and hi*lo
            #pragma unroll
            for (int mf = 0; mf < 4; ++mf)
                #pragma unroll
                for (int nf = 0; nf < 2; ++nf)
                    #pragma unroll
                    for (int j = 0; j < 2; ++j) {
                        mma_bf16(acc[mf][nf*2+j], ah[mf], bh[nf][j*2], bh[nf][j*2+1]);
                        mma_bf16(acc[mf][nf*2+j], ah[mf], bl[nf][j*2], bl[nf][j*2+1]);
                    }
            // lo*hi
            uint32_t al[4][4];
            #pragma unroll
            for (int mf = 0; mf < 4; ++mf) {
                uint32_t row = wm * 64 + mf * 16 + (lid & 15);
                uint32_t off = SWZ(row * 128 + colA);
                ldsm_x4(al[mf], aLO + off);
            }
            #pragma unroll
            for (int mf = 0; mf < 4; ++mf)
                #pragma unroll
                for (int nf = 0; nf < 2; ++nf)
                    #pragma unroll
                    for (int j = 0; j < 2; ++j)
                        mma_bf16(acc[mf][nf*2+j], al[mf], bh[nf][j*2], bh[nf][j*2+1]);
        }
    }

    // ---- epilogue ----
    const int qm = lid >> 2, qn = (lid & 3) * 2;
    #pragma unroll
    for (int mf = 0; mf < 4; ++mf)
        #pragma unroll
        for (int nf = 0; nf < 2; ++nf)
            #pragma unroll
            for (int j = 0; j < 2; ++j) {
                const float* d = acc[mf][nf*2+j];
                int nl = wn * 32 + nf * 16 + j * 8 + qn;
                int gn = nb0 + nl;
                #pragma unroll
                for (int hh = 0; hh < 2; ++hh) {
                    int ml = wm * 64 + mf * 16 + qm + hh * 8;
                    size_t row = (size_t)m0 + ml;
                    float v0 = d[hh*2+0] + sbias[nl];
                    float v1 = d[hh*2+1] + sbias[nl+1];
                    if (PHASE == 1) {
                        v0 = fmaxf(v0, 0.f); v1 = fmaxf(v1, 0.f);
                        __nv_bfloat16 h0 = __float2bfloat16(v0);
                        __nv_bfloat16 h1 = __float2bfloat16(v1);
                        *(uint32_t*)(g_ffh + row * NG + gn) = pack2(h0, h1);
                        *(uint32_t*)(g_ffl + row * NG + gn) =
                            pack2(__float2bfloat16(v0 - __bfloat162float(h0)),
                                  __float2bfloat16(v1 - __bfloat162float(h1)));
                    } else {
                        int tok = sseq[ml];
                        float2 e2 = *(const float2*)(embed + (size_t)tok * HH + gn);
                        float2 o; o.x = v0 + e2.x; o.y = v1 + e2.y;
                        *(float2*)(g_h + row * NG + gn) = o;
                    }
                }
            }
}

// ---------------- 3. LayerNorm (in place on g_h) ----------------
__global__ void k_ln(const float* __restrict__ gamma, const float* __restrict__ beta_ln) {
    size_t row = blockIdx.x;
    int tid = threadIdx.x;
    float* xp = g_h + row * HH;
    float x = xp[tid];
    __shared__ float red[8];
    float s = x;
    #pragma unroll
    for (int o = 16; o; o >>= 1) s += __shfl_xor_sync(0xffffffffu, s, o);
    if ((tid & 31) == 0) red[tid >> 5] = s;
    __syncthreads();
    float mu = 0.f;
    #pragma unroll
    for (int i = 0; i < 8; ++i) mu += red[i];
    mu *= (1.0f / HH);
    __syncthreads();
    float d = x - mu;
    float v = d * d;
    #pragma unroll
    for (int o = 16; o; o >>= 1) v += __shfl_xor_sync(0xffffffffu, v, o);
    if ((tid & 31) == 0) red[tid >> 5] = v;
    __syncthreads();
    float var = 0.f;
    #pragma unroll
    for (int i = 0; i < 8; ++i) var += red[i];
    var *= (1.0f / HH);
    xp[tid] = d * rsqrtf(var + 1e-5f) * gamma[tid] + beta_ln[tid];
}

// ---------------- 4. chunked momentum delta-rule scan ----------------
static constexpr int SCAN_SMEM_FLOATS = 128*257 + CH*257 + CH*128 + CH*CH + CH + 40;
static constexpr int SCAN_SMEM_BYTES  = SCAN_SMEM_FLOATS * 4;

__global__ __launch_bounds__(256, 1) void k_scan() {
    extern __shared__ float smf[];
    float* sM  = smf;
    float* sK  = sM + 128*257;
    float* sD  = sK + CH*257;
    float* sA  = sD + CH*128;
    float* sc  = sA + CH*CH;
    float* spw = sc + CH;

    int tid = threadIdx.x;
    int b   = blockIdx.x >> 1;
    int r0  = (blockIdx.x & 1) * 128;

    for (int i = tid; i < 128*257; i += 256) sM[i] = 0.f;
    if (tid == 0) {
        spw[0] = 1.f;
        for (int i = 1; i <= CH; ++i) spw[i] = spw[i-1] * BETA;
    }
    __syncthreads();

    const int u_ig = tid >> 3;
    const int u_tg = tid & 7;
    const int m_ig = tid & 15;
    const int m_jg = tid >> 4;

    const float* hb = g_h + (size_t)b * LL * HH;

    for (int t0 = 0; t0 < TT; t0 += CH) {
        int Cc = min(CH, TT - t0);
        __syncthreads();

        for (int idx = tid; idx < Cc * 64; idx += 256) {
            int lt = idx >> 6, q = idx & 63;
            float4 v = *(const float4*)(hb + (size_t)(t0 + lt) * HH + q * 4);
            float* dst = sK + lt*257 + q*4;
            dst[0] = v.x; dst[1] = v.y; dst[2] = v.z; dst[3] = v.w;
        }
        __syncthreads();

        int P = Cc * (Cc + 1) / 2;
        for (int p = tid; p < P; p += 256) {
            int t = (int)((sqrtf(8.f * p + 1.f) - 1.f) * 0.5f);
            while ((t + 1) * (t + 2) / 2 <= p) ++t;
            while (t * (t + 1) / 2 > p) --t;
            int s = p - t * (t + 1) / 2;
            const float* kt = sK + t*257;
            const float* ks = sK + s*257;
            float dot = 0.f;
            #pragma unroll 8
            for (int j = 0; j < HH; ++j) dot += kt[j] * ks[j];
            if (s == t) sc[t] = dot;
            else        sA[t*CH + s] = dot;
        }
        __syncthreads();
        if (tid < Cc) sc[tid] = 1.0f / (sc[tid] + 1e-6f);
        __syncthreads();
        for (int p = tid; p < P; p += 256) {
            int t = (int)((sqrtf(8.f * p + 1.f) - 1.f) * 0.5f);
            while ((t + 1) * (t + 2) / 2 <= p) ++t;
            while (t * (t + 1) / 2 > p) --t;
            int s = p - t * (t + 1) / 2;
            if (s < t) sA[t*CH + s] *= sc[t] * OMB * spw[t - 1 - s];
        }
        __syncthreads();

        {
            int i0 = u_ig * 4, lt0 = u_tg * 4;
            float acc[4][4];
            #pragma unroll
            for (int r = 0; r < 4; ++r)
                #pragma unroll
                for (int c = 0; c < 4; ++c) acc[r][c] = 0.f;
            #pragma unroll 4
            for (int j = 0; j < HH; ++j) {
                float a0 = sM[(i0+0)*257 + j], a1 = sM[(i0+1)*257 + j];
                float a2 = sM[(i0+2)*257 + j], a3 = sM[(i0+3)*257 + j];
                float b0 = sK[(lt0+0)*257 + j], b1 = sK[(lt0+1)*257 + j];
                float b2 = sK[(lt0+2)*257 + j], b3 = sK[(lt0+3)*257 + j];
                acc[0][0] += a0*b0; acc[0][1] += a0*b1; acc[0][2] += a0*b2; acc[0][3] += a0*b3;
                acc[1][0] += a1*b0; acc[1][1] += a1*b1; acc[1][2] += a1*b2; acc[1][3] += a1*b3;
                acc[2][0] += a2*b0; acc[2][1] += a2*b1; acc[2][2] += a2*b2; acc[2][3] += a2*b3;
                acc[3][0] += a3*b0; acc[3][1] += a3*b1; acc[3][2] += a3*b2; acc[3][3] += a3*b3;
            }
            #pragma unroll
            for (int c = 0; c < 4; ++c) {
                int lt = lt0 + c;
                if (lt < Cc) {
                    float coef = sc[lt] * spw[lt];
                    #pragma unroll
                    for (int r = 0; r < 4; ++r) {
                        int i = i0 + r;
                        sD[lt*128 + i] = sK[lt*257 + r0 + i] - coef * acc[r][c];
                    }
                }
            }
        }
        __syncthreads();

        {
            int i  = tid & 127;
            int tg = tid >> 7;
            for (int s = 0; s < Cc - 1; ++s) {
                __syncthreads();
                float ds = sD[s*128 + i];
                for (int t = s + 1 + tg; t < Cc; t += 2)
                    sD[t*128 + i] -= sA[t*CH + s] * ds;
            }
            __syncthreads();
        }

        {
            float bc = spw[Cc];
            int i0 = m_ig * 8, j0 = m_jg * 16;
            float acc[8][16];
            #pragma unroll
            for (int r = 0; r < 8; ++r)
                #pragma unroll
                for (int c = 0; c < 16; ++c)
                    acc[r][c] = sM[(i0+r)*257 + j0 + c] * bc;
            for (int s = 0; s < Cc; ++s) {
                float w = OMB * spw[Cc - 1 - s];
                float4 d0 = *(const float4*)(sD + s*128 + i0);
                float4 d1 = *(const float4*)(sD + s*128 + i0 + 4);
                float dr[8] = {d0.x*w, d0.y*w, d0.z*w, d0.w*w,
                               d1.x*w, d1.y*w, d1.z*w, d1.w*w};
                #pragma unroll
                for (int c = 0; c < 16; ++c) {
                    float kv = sK[s*257 + j0 + c];
                    #pragma unroll
                    for (int r = 0; r < 8; ++r) acc[r][c] += dr[r] * kv;
                }
            }
            #pragma unroll
            for (int r = 0; r < 8; ++r)
                #pragma unroll
                for (int c = 0; c < 16; ++c)
                    sM[(i0+r)*257 + j0 + c] = acc[r][c];
        }
    }

    __syncthreads();
    for (int idx = tid; idx < 128 * HH; idx += 256) {
        int i = idx >> 8, j = idx & 255;
        g_M[((size_t)b * HH + r0 + i) * HH + j] = sM[i*257 + j];
    }
}

// ---------------- 5. readout: y = M h_last ----------------
__global__ void k_read1() {
    int b = blockIdx.x;
    int tid = threadIdx.x;
    __shared__ float hl[HH];
    hl[tid] = g_h[((size_t)b * LL + (LL - 1)) * HH + tid];
    __syncthreads();
    int w = tid >> 5, lane = tid & 31;
    for (int i = w; i < HH; i += 8) {
        const float* Mr = g_M + ((size_t)b * HH + i) * HH;
        float s = 0.f;
        #pragma unroll
        for (int j = lane; j < HH; j += 32) s += Mr[j] * hl[j];
        #pragma unroll
        for (int o = 16; o; o >>= 1) s += __shfl_xor_sync(0xffffffffu, s, o);
        if (lane == 0) g_y[b * HH + i] = s;
    }
}

// ---------------- 6. y2 = y @ rp_W + rp_b ----------------
__global__ void k_read2(const float* __restrict__ rp_W, const float* __restrict__ rp_b) {
    int b = blockIdx.x, n = threadIdx.x;
    __shared__ float ys[HH];
    ys[n] = g_y[b * HH + n];
    __syncthreads();
    float acc = rp_b[n];
    #pragma unroll 4
    for (int k = 0; k < HH; ++k) acc += ys[k] * rp_W[k * HH + n];
    g_y2[b * HH + n] = acc;
}

// ---------------- 7. out = y2 @ out_W + out_b ----------------
static constexpr int OUT_SMEM_BYTES = (HH * 128 + BB * 257) * 4;

__global__ __launch_bounds__(256) void k_out(
    const float* __restrict__ out_W, const float* __restrict__ out_b,
    float* __restrict__ out)
{
    extern __shared__ float smf[];
    float* sW  = smf;
    float* sy2 = smf + HH * 128;
    int tid = threadIdx.x;
    int n_base = blockIdx.x * 128;

    for (int idx = tid; idx < HH * 32; idx += 256) {
        int k = idx >> 5, q = idx & 31;
        *(float4*)(sW + k*128 + q*4) = *(const float4*)(out_W + (size_t)k * VV + n_base + q*4);
    }
    for (int idx = tid; idx < BB * 64; idx += 256) {
        int bb = idx >> 6, q = idx & 63;
        float4 v = *(const float4*)(g_y2 + bb * HH + q*4);
        float* d = sy2 + bb*257 + q*4;
        d[0] = v.x; d[1] = v.y; d[2] = v.z; d[3] = v.w;
    }
    __syncthreads();

    int bg = tid >> 4, ng = tid & 15;
    int b0 = bg * 4, n0 = ng * 8;
    float acc[4][8];
    #pragma unroll
    for (int r = 0; r < 4; ++r)
        #pragma unroll
        for (int c = 0; c < 8; ++c) acc[r][c] = 0.f;
    for (int k = 0; k < HH; ++k) {
        float4 w0 = *(const float4*)(sW + k*128 + n0);
        float4 w1 = *(const float4*)(sW + k*128 + n0 + 4);
        float wv[8] = {w0.x, w0.y, w0.z, w0.w, w1.x, w1.y, w1.z, w1.w};
        #pragma unroll
        for (int r = 0; r < 4; ++r) {
            float yv = sy2[(b0+r)*257 + k];
            #pragma unroll
            for (int c = 0; c < 8; ++c) acc[r][c] += yv * wv[c];
        }
    }
    #pragma unroll
    for (int r = 0; r < 4; ++r)
        #pragma unroll
        for (int c = 0; c < 8; ++c)
            out[(size_t)(b0+r) * VV + n_base + n0 + c] = acc[r][c] + out_b[n_base + n0 + c];
}

// ---------------- launch ----------------
extern "C" void kernel_launch(void* const* d_in, const int* in_sizes, int n_in,
                              void* d_out, int out_size) {
    (void)in_sizes; (void)n_in; (void)out_size;
    const int*   seq     = (const int*)  d_in[0];
    const float* embed   = (const float*)d_in[1];
    const float* W1      = (const float*)d_in[2];
    const float* b1      = (const float*)d_in[3];
    const float* W2      = (const float*)d_in[4];
    const float* b2      = (const float*)d_in[5];
    const float* gamma   = (const float*)d_in[6];
    const float* beta_ln = (const float*)d_in[7];
    const float* rp_W    = (const float*)d_in[8];
    const float* rp_b    = (const float*)d_in[9];
    const float* out_W   = (const float*)d_in[10];
    const float* out_b   = (const float*)d_in[11];
    float* out = (float*)d_out;

    cudaFuncSetAttribute(k_ffn<1>, cudaFuncAttributeMaxDynamicSharedMemorySize, FFN_SMEM);
    cudaFuncSetAttribute(k_ffn<2>, cudaFuncAttributeMaxDynamicSharedMemorySize, FFN_SMEM);
    cudaFuncSetAttribute(k_scan,   cudaFuncAttributeMaxDynamicSharedMemorySize, SCAN_SMEM_BYTES);
    cudaFuncSetAttribute(k_out,    cudaFuncAttributeMaxDynamicSharedMemorySize, OUT_SMEM_BYTES);

    // 0. weight transpose + bf16 split
    k_prep<<<512, 256>>>(W1, W2);
    // 1. ff = relu(gather @ W1 + b1)   (HMMA, gather fused)
    k_ffn<1><<<dim3(4, BB*LL/128), 256, FFN_SMEM>>>(seq, embed, b1);
    // 2. x = ff @ W2 + b2 + e          (HMMA, residual gather fused)
    k_ffn<2><<<dim3(2, BB*LL/128), 256, FFN_SMEM>>>(seq, embed, b2);
    // 3. h = LayerNorm(x) in place
    k_ln<<<BB * LL, HH>>>(gamma, beta_ln);
    // 4. chunked delta-rule scan
    k_scan<<<BB * 2, 256, SCAN_SMEM_BYTES>>>();
    // 5-7. readout
    k_read1<<<BB, 256>>>();
    k_read2<<<BB, HH>>>(rp_W, rp_b);
    k_out<<<VV / 128, 256, OUT_SMEM_BYTES>>>(out_W, out_b, out);
}

// round 4
// speedup vs baseline: 1.1795x; 1.0359x over previous
#include <cuda_runtime.h>
#include <cuda_bf16.h>
#include <math.h>
#include <stdint.h>

static constexpr int BB = 64;
static constexpr int LL = 2048;
static constexpr int HH = 256;
static constexpr int VV = 32000;
static constexpr int TT = LL - 1;
static constexpr float BETA = 0.9f;
static constexpr float OMB  = 0.1f;
static constexpr int CH = 32;

// ---------------- scratch (device globals) ----------------
__device__ float g_h [(size_t)BB*LL*HH];               // x then LayerNorm(h)
__device__ __nv_bfloat16 g_ah [(size_t)BB*LL*HH];      // gathered embed hi
__device__ __nv_bfloat16 g_al [(size_t)BB*LL*HH];      // gathered embed lo
__device__ __nv_bfloat16 g_ffh[(size_t)BB*LL*2*HH];    // relu(e@W1+b1) hi
__device__ __nv_bfloat16 g_ffl[(size_t)BB*LL*2*HH];    // lo
__device__ __nv_bfloat16 g_w1h[512*256], g_w1l[512*256];   // W1^T [N=512][K=256]
__device__ __nv_bfloat16 g_w2h[256*512], g_w2l[256*512];   // W2^T [N=256][K=512]
__device__ float g_M [(size_t)BB*HH*HH];
__device__ float g_y [BB*HH];
__device__ float g_y2[BB*HH];

// ---------------- helpers ----------------
#define SWZ(o) ((o) ^ (((o) >> 3) & 0x70))

__device__ __forceinline__ uint32_t smem_u32(const void* p) {
    uint32_t a;
    asm("{ .reg .u64 t; cvta.to.shared.u64 t, %1; cvt.u32.u64 %0, t; }" : "=r"(a) : "l"(p));
    return a;
}
__device__ __forceinline__ uint32_t pack2(__nv_bfloat16 a, __nv_bfloat16 b) {
    __nv_bfloat162 t = __halves2bfloat162(a, b);
    return *reinterpret_cast<uint32_t*>(&t);
}
__device__ __forceinline__ void ldsm_x4(uint32_t* r, uint32_t addr) {
    asm volatile("ldmatrix.sync.aligned.m8n8.x4.shared.b16 {%0,%1,%2,%3}, [%4];"
        : "=r"(r[0]), "=r"(r[1]), "=r"(r[2]), "=r"(r[3]) : "r"(addr));
}
__device__ __forceinline__ void mma_bf16(float* d, const uint32_t* a, uint32_t b0, uint32_t b1) {
    asm volatile("mma.sync.aligned.m16n8k16.row.col.f32.bf16.bf16.f32 "
        "{%0,%1,%2,%3}, {%4,%5,%6,%7}, {%8,%9}, {%0,%1,%2,%3};"
        : "+f"(d[0]), "+f"(d[1]), "+f"(d[2]), "+f"(d[3])
        : "r"(a[0]), "r"(a[1]), "r"(a[2]), "r"(a[3]), "r"(b0), "r"(b1));
}
__device__ __forceinline__ void cp16(uint32_t dst, const void* src) {
    asm volatile("cp.async.cg.shared.global [%0], [%1], 16;" :: "r"(dst), "l"(src));
}

// ---------------- 0a. weight transpose + bf16 split ----------------
__global__ void k_prep(const float* __restrict__ W1, const float* __restrict__ W2) {
    int idx = blockIdx.x * blockDim.x + threadIdx.x;   // 0 .. 131071
    {   // W1t [n=512][k=256] = W1[k][n]
        int n = idx >> 8, k = idx & 255;
        float w = W1[k * 512 + n];
        __nv_bfloat16 h = __float2bfloat16(w);
        g_w1h[idx] = h;
        g_w1l[idx] = __float2bfloat16(w - __bfloat162float(h));
    }
    {   // W2t [n=256][k=512] = W2[k][n]
        int n = idx >> 9, k = idx & 511;
        float w = W2[k * 256 + n];
        __nv_bfloat16 h = __float2bfloat16(w);
        g_w2h[idx] = h;
        g_w2l[idx] = __float2bfloat16(w - __bfloat162float(h));
    }
}

// ---------------- 0b. embedding gather + bf16 split ----------------
__global__ void k_split(const int* __restrict__ seq, const float* __restrict__ embed) {
    size_t idx = (size_t)blockIdx.x * blockDim.x + threadIdx.x;   // over B*L*64 quads
    int row = (int)(idx >> 6), q = (int)(idx & 63);
    int tok = seq[row];
    float4 v = ((const float4*)embed)[(size_t)tok * 64 + q];
    __nv_bfloat16 h0 = __float2bfloat16(v.x), h1 = __float2bfloat16(v.y);
    __nv_bfloat16 h2 = __float2bfloat16(v.z), h3 = __float2bfloat16(v.w);
    ((uint2*)g_ah)[idx] = make_uint2(pack2(h0, h1), pack2(h2, h3));
    ((uint2*)g_al)[idx] = make_uint2(
        pack2(__float2bfloat16(v.x - __bfloat162float(h0)),
              __float2bfloat16(v.y - __bfloat162float(h1))),
        pack2(__float2bfloat16(v.z - __bfloat162float(h2)),
              __float2bfloat16(v.w - __bfloat162float(h3))));
}

// ---------------- 1+2. FFN GEMMs, HMMA + cp.async 2-stage pipeline ----------------
// PHASE 1: ff = relu(A @ W1 + b1) -> g_ffh/g_ffl   (M=131072, N=512, K=256)
// PHASE 2: x  = ff @ W2 + b2 + e  -> g_h           (M=131072, N=256, K=512)
// CTA tile 128x128, 8 warps (2m x 4n), warp tile 64x32, K chunk 64 (SW128 smem).
static constexpr int FFN_SMEM = 1024 + 2 * 65536;   // 132096 B

struct FragAcc { float a[4][4][4]; };

__device__ __forceinline__ void ffn_compute(
    uint32_t aHI, uint32_t aLO, uint32_t bHI, uint32_t bLO,
    int wm, int wn, int lid, float (&acc)[4][4][4])
{
    #pragma unroll
    for (int ks = 0; ks < 4; ++ks) {
        uint32_t colA = ks * 32 + ((lid >> 4) << 4);
        uint32_t ah[4][4];
        #pragma unroll
        for (int mf = 0; mf < 4; ++mf) {
            uint32_t row = wm * 64 + mf * 16 + (lid & 15);
            ldsm_x4(ah[mf], aHI + SWZ(row * 128 + colA));
        }
        uint32_t bh[2][4], bl[2][4];
        #pragma unroll
        for (int nf = 0; nf < 2; ++nf) {
            uint32_t row = wn * 32 + nf * 16 + ((lid >> 4) << 3) + (lid & 7);
            uint32_t colB = ks * 32 + (((lid >> 3) & 1) << 4);
            ldsm_x4(bh[nf], bHI + SWZ(row * 128 + colB));
            ldsm_x4(bl[nf], bLO + SWZ(row * 128 + colB));
        }
        #pragma unroll
        for (int mf = 0; mf < 4; ++mf)
            #pragma unroll
            for (int nf = 0; nf < 2; ++nf)
                #pragma unroll
                for (int j = 0; j < 2; ++j) {
                    mma_bf16(acc[mf][nf*2+j], ah[mf], bh[nf][j*2], bh[nf][j*2+1]);
                    mma_bf16(acc[mf][nf*2+j], ah[mf], bl[nf][j*2], bl[nf][j*2+1]);
                }
        uint32_t al[4][4];
        #pragma unroll
        for (int mf = 0; mf < 4; ++mf) {
            uint32_t row = wm * 64 + mf * 16 + (lid & 15);
            ldsm_x4(al[mf], aLO + SWZ(row * 128 + colA));
        }
        #pragma unroll
        for (int mf = 0; mf < 4; ++mf)
            #pragma unroll
            for (int nf = 0; nf < 2; ++nf)
                #pragma unroll
                for (int j = 0; j < 2; ++j)
                    mma_bf16(acc[mf][nf*2+j], al[mf], bh[nf][j*2], bh[nf][j*2+1]);
    }
}

template<int PHASE>
__global__ __launch_bounds__(256) void k_ffn(
    const int* __restrict__ seq, const float* __restrict__ embed,
    const float* __restrict__ bias)
{
    constexpr int K   = (PHASE == 1) ? HH : 2 * HH;
    constexpr int NC  = K / 64;
    constexpr int ARS = (PHASE == 1) ? HH : 2 * HH;   // A row stride (elems)

    extern __shared__ char sm[];
    int*   sseq  = (int*)sm;              // 128 ints (phase 2 only)
    float* sbias = (float*)(sm + 512);    // 128 floats
    char* st0 = sm + 1024;
    char* st1 = sm + 1024 + 65536;

    const int tid = threadIdx.x, wid = tid >> 5, lid = tid & 31;
    const int wm = wid & 1, wn = wid >> 1;
    const int m0  = blockIdx.y * 128;
    const int nb0 = blockIdx.x * 128;

    const __nv_bfloat16* Ah = (PHASE == 1) ? g_ah  : g_ffh;
    const __nv_bfloat16* Al = (PHASE == 1) ? g_al  : g_ffl;
    const __nv_bfloat16* Wh = (PHASE == 1) ? g_w1h : g_w2h;
    const __nv_bfloat16* Wl = (PHASE == 1) ? g_w1l : g_w2l;

    if (tid < 128) {
        sbias[tid] = bias[nb0 + tid];
        if (PHASE == 2) sseq[tid] = seq[m0 + tid];
    }

    // issue loads of chunk c into stage st
    const int a_row = tid >> 1, a_half = tid & 1;
    const int b_row = tid & 127, b_sel = tid >> 7;
    auto issue = [&](int c, char* st) {
        int k0 = c * 64;
        uint32_t aH = smem_u32(st), aL = aH + 16384, bH = aL + 16384, bL = bH + 16384;
        const char* asrcH = (const char*)(Ah + (size_t)(m0 + a_row) * ARS + k0) + a_half * 64;
        const char* asrcL = (const char*)(Al + (size_t)(m0 + a_row) * ARS + k0) + a_half * 64;
        #pragma unroll
        for (int j = 0; j < 4; ++j) {
            uint32_t off = SWZ((uint32_t)(a_row * 128 + a_half * 64 + j * 16));
            cp16(aH + off, asrcH + j * 16);
            cp16(aL + off, asrcL + j * 16);
        }
        const __nv_bfloat16* w = b_sel ? Wl : Wh;
        uint32_t bb = b_sel ? bL : bH;
        const char* bsrc = (const char*)(w + (size_t)(nb0 + b_row) * K + k0);
        #pragma unroll
        for (int j = 0; j < 8; ++j)
            cp16(bb + SWZ((uint32_t)(b_row * 128 + j * 16)), bsrc + j * 16);
        asm volatile("cp.async.commit_group;" ::: "memory");
    };

    float acc[4][4][4];
    #pragma unroll
    for (int a = 0; a < 4; ++a)
        #pragma unroll
        for (int b = 0; b < 4; ++b)
            #pragma unroll
            for (int c = 0; c < 4; ++c) acc[a][b][c] = 0.f;

    issue(0, st0);
    for (int c = 0; c < NC; ++c) {
        char* cur = (c & 1) ? st1 : st0;
        if (c + 1 < NC) {
            issue(c + 1, ((c + 1) & 1) ? st1 : st0);
            asm volatile("cp.async.wait_group 1;" ::: "memory");
        } else {
            asm volatile("cp.async.wait_group 0;" ::: "memory");
        }
        __syncthreads();
        uint32_t aH = smem_u32(cur);
        ffn_compute(aH, aH + 16384, aH + 32768, aH + 49152, wm, wn, lid, acc);
        __syncthreads();
    }

    // ---- epilogue: stage to smem, then coalesced global writes ----
    const int qm = lid >> 2, qn = (lid & 3) * 2;
    if (PHASE == 1) {
        uint32_t* SH = (uint32_t*)(sm + 1024);           // [128][64] packed bf16x2
        uint32_t* SL = SH + 8192;
        #pragma unroll
        for (int mf = 0; mf < 4; ++mf)
            #pragma unroll
            for (int nf = 0; nf < 2; ++nf)
                #pragma unroll
                for (int j = 0; j < 2; ++j) {
                    const float* d = acc[mf][nf*2+j];
                    int nl = wn * 32 + nf * 16 + j * 8 + qn;
                    #pragma unroll
                    for (int hh = 0; hh < 2; ++hh) {
                        int ml = wm * 64 + mf * 16 + qm + hh * 8;
                        float v0 = fmaxf(d[hh*2+0] + sbias[nl],   0.f);
                        float v1 = fmaxf(d[hh*2+1] + sbias[nl+1], 0.f);
                        __nv_bfloat16 h0 = __float2bfloat16(v0);
                        __nv_bfloat16 h1 = __float2bfloat16(v1);
                        SH[ml * 64 + (nl >> 1)] = pack2(h0, h1);
                        SL[ml * 64 + (nl >> 1)] =
                            pack2(__float2bfloat16(v0 - __bfloat162float(h0)),
                                  __float2bfloat16(v1 - __bfloat162float(h1)));
                    }
                }
        __syncthreads();
        int row = tid >> 1, part = tid & 1;
        const uint4* shp = (const uint4*)SH;
        const uint4* slp = (const uint4*)SL;
        uint4* gh = (uint4*)(g_ffh + (size_t)(m0 + row) * 512 + nb0);
        uint4* gl = (uint4*)(g_ffl + (size_t)(m0 + row) * 512 + nb0);
        #pragma unroll
        for (int j = 0; j < 8; ++j) {
            int q = part * 8 + j;
            gh[q] = shp[row * 16 + q];
            gl[q] = slp[row * 16 + q];
        }
    } else {
        float* SF = (float*)(sm + 1024);                 // [128][128] f32
        #pragma unroll
        for (int mf = 0; mf < 4; ++mf)
            #pragma unroll
            for (int nf = 0; nf < 2; ++nf)
                #pragma unroll
                for (int j = 0; j < 2; ++j) {
                    const float* d = acc[mf][nf*2+j];
                    int nl = wn * 32 + nf * 16 + j * 8 + qn;
                    #pragma unroll
                    for (int hh = 0; hh < 2; ++hh) {
                        int ml = wm * 64 + mf * 16 + qm + hh * 8;
                        SF[ml * 128 + nl]     = d[hh*2+0] + sbias[nl];
                        SF[ml * 128 + nl + 1] = d[hh*2+1] + sbias[nl+1];
                    }
                }
        __syncthreads();
        int row = tid >> 1, part = tid & 1;
        int tok = sseq[row];
        const float4* ep = (const float4*)(embed + (size_t)tok * HH + nb0);
        const float4* sfp = (const float4*)(SF + row * 128);
        float4* gp = (float4*)(g_h + (size_t)(m0 + row) * HH + nb0);
        #pragma unroll
        for (int j = 0; j < 16; ++j) {
            int c4 = part * 16 + j;
            float4 f = sfp[c4];
            float4 e = ep[c4];
            f.x += e.x; f.y += e.y; f.z += e.z; f.w += e.w;
            gp[c4] = f;
        }
    }
}

// ---------------- 3. LayerNorm: one warp per row, float4 ----------------
__global__ void k_ln(const float* __restrict__ gamma, const float* __restrict__ beta_ln) {
    int warp = threadIdx.x >> 5, lane = threadIdx.x & 31;
    size_t row = (size_t)blockIdx.x * 8 + warp;
    float4* xp = (float4*)(g_h + row * HH);
    float4 a = xp[lane * 2];
    float4 b = xp[lane * 2 + 1];
    float s = a.x + a.y + a.z + a.w + b.x + b.y + b.z + b.w;
    #pragma unroll
    for (int o = 16; o; o >>= 1) s += __shfl_xor_sync(0xffffffffu, s, o);
    float mu = s * (1.0f / HH);
    float dx[8] = {a.x-mu, a.y-mu, a.z-mu, a.w-mu, b.x-mu, b.y-mu, b.z-mu, b.w-mu};
    float v = 0.f;
    #pragma unroll
    for (int q = 0; q < 8; ++q) v += dx[q] * dx[q];
    #pragma unroll
    for (int o = 16; o; o >>= 1) v += __shfl_xor_sync(0xffffffffu, v, o);
    float inv = rsqrtf(v * (1.0f / HH) + 1e-5f);
    float4 g0 = ((const float4*)gamma)[lane * 2];
    float4 g1 = ((const float4*)gamma)[lane * 2 + 1];
    float4 t0 = ((const float4*)beta_ln)[lane * 2];
    float4 t1 = ((const float4*)beta_ln)[lane * 2 + 1];
    float4 o0, o1;
    o0.x = dx[0]*inv*g0.x + t0.x; o0.y = dx[1]*inv*g0.y + t0.y;
    o0.z = dx[2]*inv*g0.z + t0.z; o0.w = dx[3]*inv*g0.w + t0.w;
    o1.x = dx[4]*inv*g1.x + t1.x; o1.y = dx[5]*inv*g1.y + t1.y;
    o1.z = dx[6]*inv*g1.z + t1.z; o1.w = dx[7]*inv*g1.w + t1.w;
    xp[lane * 2]     = o0;
    xp[lane * 2 + 1] = o1;
}

// ---------------- 4. chunked momentum delta-rule scan ----------------
static constexpr int SCAN_SMEM_FLOATS = 128*257 + CH*257 + CH*128 + CH*CH + CH + 40;
static constexpr int SCAN_SMEM_BYTES  = SCAN_SMEM_FLOATS * 4;

__global__ __launch_bounds__(256, 1) void k_scan() {
    extern __shared__ float smf[];
    float* sM  = smf;
    float* sK  = sM + 128*257;
    float* sD  = sK + CH*257;
    float* sA  = sD + CH*128;
    float* sc  = sA + CH*CH;
    float* spw = sc + CH;

    int tid = threadIdx.x;
    int b   = blockIdx.x >> 1;
    int r0  = (blockIdx.x & 1) * 128;

    for (int i = tid; i < 128*257; i += 256) sM[i] = 0.f;
    if (tid == 0) {
        spw[0] = 1.f;
        for (int i = 1; i <= CH; ++i) spw[i] = spw[i-1] * BETA;
    }
    __syncthreads();

    const int u_ig = tid >> 3;
    const int u_tg = tid & 7;
    const int m_ig = tid & 15;
    const int m_jg = tid >> 4;

    const float* hb = g_h + (size_t)b * LL * HH;

    for (int t0 = 0; t0 < TT; t0 += CH) {
        int Cc = min(CH, TT - t0);
        __syncthreads();

        for (int idx = tid; idx < Cc * 64; idx += 256) {
            int lt = idx >> 6, q = idx & 63;
            float4 v = *(const float4*)(hb + (size_t)(t0 + lt) * HH + q * 4);
            float* dst = sK + lt*257 + q*4;
            dst[0] = v.x; dst[1] = v.y; dst[2] = v.z; dst[3] = v.w;
        }
        __syncthreads();

        int P = Cc * (Cc + 1) / 2;
        for (int p = tid; p < P; p += 256) {
            int t = (int)((sqrtf(8.f * p + 1.f) - 1.f) * 0.5f);
            while ((t + 1) * (t + 2) / 2 <= p) ++t;
            while (t * (t + 1) / 2 > p) --t;
            int s = p - t * (t + 1) / 2;
            const float* kt = sK + t*257;
            const float* ks = sK + s*257;
            float dot = 0.f;
            #pragma unroll 8
            for (int j = 0; j < HH; ++j) dot += kt[j] * ks[j];
            if (s == t) sc[t] = dot;
            else        sA[t*CH + s] = dot;
        }
        __syncthreads();
        if (tid < Cc) sc[tid] = 1.0f / (sc[tid] + 1e-6f);
        __syncthreads();
        for (int p = tid; p < P; p += 256) {
            int t = (int)((sqrtf(8.f * p + 1.f) - 1.f) * 0.5f);
            while ((t + 1) * (t + 2) / 2 <= p) ++t;
            while (t * (t + 1) / 2 > p) --t;
            int s = p - t * (t + 1) / 2;
            if (s < t) sA[t*CH + s] *= sc[t] * OMB * spw[t - 1 - s];
        }
        __syncthreads();

        {
            int i0 = u_ig * 4, lt0 = u_tg * 4;
            float acc[4][4];
            #pragma unroll
            for (int r = 0; r < 4; ++r)
                #pragma unroll
                for (int c = 0; c < 4; ++c) acc[r][c] = 0.f;
            #pragma unroll 4
            for (int j = 0; j < HH; ++j) {
                float a0 = sM[(i0+0)*257 + j], a1 = sM[(i0+1)*257 + j];
                float a2 = sM[(i0+2)*257 + j], a3 = sM[(i0+3)*257 + j];
                float b0 = sK[(lt0+0)*257 + j], b1 = sK[(lt0+1)*257 + j];
                float b2 = sK[(lt0+2)*257 + j], b3 = sK[(lt0+3)*257 + j];
                acc[0][0] += a0*b0; acc[0][1] += a0*b1; acc[0][2] += a0*b2; acc[0][3] += a0*b3;
                acc[1][0] += a1*b0; acc[1][1] += a1*b1; acc[1][2] += a1*b2; acc[1][3] += a1*b3;
                acc[2][0] += a2*b0; acc[2][1] += a2*b1; acc[2][2] += a2*b2; acc[2][3] += a2*b3;
                acc[3][0] += a3*b0; acc[3][1] += a3*b1; acc[3][2] += a3*b2; acc[3][3] += a3*b3;
            }
            #pragma unroll
            for (int c = 0; c < 4; ++c) {
                int lt = lt0 + c;
                if (lt < Cc) {
                    float coef = sc[lt] * spw[lt];
                    #pragma unroll
                    for (int r = 0; r < 4; ++r) {
                        int i = i0 + r;
                        sD[lt*128 + i] = sK[lt*257 + r0 + i] - coef * acc[r][c];
                    }
                }
            }
        }
        __syncthreads();

        {
            int i  = tid & 127;
            int tg = tid >> 7;
            for (int s = 0; s < Cc - 1; ++s) {
                __syncthreads();
                float ds = sD[s*128 + i];
                for (int t = s + 1 + tg; t < Cc; t += 2)
                    sD[t*128 + i] -= sA[t*CH + s] * ds;
            }
            __syncthreads();
        }

        {
            float bc = spw[Cc];
            int i0 = m_ig * 8, j0 = m_jg * 16;
            float acc[8][16];
            #pragma unroll
            for (int r = 0; r < 8; ++r)
                #pragma unroll
                for (int c = 0; c < 16; ++c)
                    acc[r][c] = sM[(i0+r)*257 + j0 + c] * bc;
            for (int s = 0; s < Cc; ++s) {
                float w = OMB * spw[Cc - 1 - s];
                float4 d0 = *(const float4*)(sD + s*128 + i0);
                float4 d1 = *(const float4*)(sD + s*128 + i0 + 4);
                float dr[8] = {d0.x*w, d0.y*w, d0.z*w, d0.w*w,
                               d1.x*w, d1.y*w, d1.z*w, d1.w*w};
                #pragma unroll
                for (int c = 0; c < 16; ++c) {
                    float kv = sK[s*257 + j0 + c];
                    #pragma unroll
                    for (int r = 0; r < 8; ++r) acc[r][c] += dr[r] * kv;
                }
            }
            #pragma unroll
            for (int r = 0; r < 8; ++r)
                #pragma unroll
                for (int c = 0; c < 16; ++c)
                    sM[(i0+r)*257 + j0 + c] = acc[r][c];
        }
    }

    __syncthreads();
    for (int idx = tid; idx < 128 * HH; idx += 256) {
        int i = idx >> 8, j = idx & 255;
        g_M[((size_t)b * HH + r0 + i) * HH + j] = sM[i*257 + j];
    }
}

// ---------------- 5. readout: y = M h_last ----------------
__global__ void k_read1() {
    int b = blockIdx.x;
    int tid = threadIdx.x;
    __shared__ float hl[HH];
    hl[tid] = g_h[((size_t)b * LL + (LL - 1)) * HH + tid];
    __syncthreads();
    int w = tid >> 5, lane = tid & 31;
    for (int i = w; i < HH; i += 8) {
        const float* Mr = g_M + ((size_t)b * HH + i) * HH;
        float s = 0.f;
        #pragma unroll
        for (int j = lane; j < HH; j += 32) s += Mr[j] * hl[j];
        #pragma unroll
        for (int o = 16; o; o >>= 1) s += __shfl_xor_sync(0xffffffffu, s, o);
        if (lane == 0) g_y[b * HH + i] = s;
    }
}

// ---------------- 6. y2 = y @ rp_W + rp_b ----------------
__global__ void k_read2(const float* __restrict__ rp_W, const float* __restrict__ rp_b) {
    int b = blockIdx.x, n = threadIdx.x;
    __shared__ float ys[HH];
    ys[n] = g_y[b * HH + n];
    __syncthreads();
    float acc = rp_b[n];
    #pragma unroll 4
    for (int k = 0; k < HH; ++k) acc += ys[k] * rp_W[k * HH + n];
    g_y2[b * HH + n] = acc;
}

// ---------------- 7. out = y2 @ out_W + out_b ----------------
static constexpr int OUT_SMEM_BYTES = (HH * 128 + BB * 257) * 4;

__global__ __launch_bounds__(256) void k_out(
    const float* __restrict__ out_W, const float* __restrict__ out_b,
    float* __restrict__ out)
{
    extern __shared__ float smf[];
    float* sW  = smf;
    float* sy2 = smf + HH * 128;
    int tid = threadIdx.x;
    int n_base = blockIdx.x * 128;

    for (int idx = tid; idx < HH * 32; idx += 256) {
        int k = idx >> 5, q = idx & 31;
        *(float4*)(sW + k*128 + q*4) = *(const float4*)(out_W + (size_t)k * VV + n_base + q*4);
    }
    for (int idx = tid; idx < BB * 64; idx += 256) {
        int bb = idx >> 6, q = idx & 63;
        float4 v = *(const float4*)(g_y2 + bb * HH + q*4);
        float* d = sy2 + bb*257 + q*4;
        d[0] = v.x; d[1] = v.y; d[2] = v.z; d[3] = v.w;
    }
    __syncthreads();

    int bg = tid >> 4, ng = tid & 15;
    int b0 = bg * 4, n0 = ng * 8;
    float acc[4][8];
    #pragma unroll
    for (int r = 0; r < 4; ++r)
        #pragma unroll
        for (int c = 0; c < 8; ++c) acc[r][c] = 0.f;
    for (int k = 0; k < HH; ++k) {
        float4 w0 = *(const float4*)(sW + k*128 + n0);
        float4 w1 = *(const float4*)(sW + k*128 + n0 + 4);
        float wv[8] = {w0.x, w0.y, w0.z, w0.w, w1.x, w1.y, w1.z, w1.w};
        #pragma unroll
        for (int r = 0; r < 4; ++r) {
            float yv = sy2[(b0+r)*257 + k];
            #pragma unroll
            for (int c = 0; c < 8; ++c) acc[r][c] += yv * wv[c];
        }
    }
    #pragma unroll
    for (int r = 0; r < 4; ++r)
        #pragma unroll
        for (int c = 0; c < 8; ++c)
            out[(size_t)(b0+r) * VV + n_base + n0 + c] = acc[r][c] + out_b[n_base + n0 + c];
}

// ---------------- launch ----------------
extern "C" void kernel_launch(void* const* d_in, const int* in_sizes, int n_in,
                              void* d_out, int out_size) {
    (void)in_sizes; (void)n_in; (void)out_size;
    const int*   seq     = (const int*)  d_in[0];
    const float* embed   = (const float*)d_in[1];
    const float* W1      = (const float*)d_in[2];
    const float* b1      = (const float*)d_in[3];
    const float* W2      = (const float*)d_in[4];
    const float* b2      = (const float*)d_in[5];
    const float* gamma   = (const float*)d_in[6];
    const float* beta_ln = (const float*)d_in[7];
    const float* rp_W    = (const float*)d_in[8];
    const float* rp_b    = (const float*)d_in[9];
    const float* out_W   = (const float*)d_in[10];
    const float* out_b   = (const float*)d_in[11];
    float* out = (float*)d_out;

    cudaFuncSetAttribute(k_ffn<1>, cudaFuncAttributeMaxDynamicSharedMemorySize, FFN_SMEM);
    cudaFuncSetAttribute(k_ffn<2>, cudaFuncAttributeMaxDynamicSharedMemorySize, FFN_SMEM);
    cudaFuncSetAttribute(k_scan,   cudaFuncAttributeMaxDynamicSharedMemorySize, SCAN_SMEM_BYTES);
    cudaFuncSetAttribute(k_out,    cudaFuncAttributeMaxDynamicSharedMemorySize, OUT_SMEM_BYTES);

    // 0. weight split + embedding gather/split
    k_prep<<<512, 256>>>(W1, W2);
    k_split<<<BB * LL * 64 / 256, 256>>>(seq, embed);
    // 1. ff = relu(A @ W1 + b1)   (HMMA, cp.async pipelined)
    k_ffn<1><<<dim3(4, BB*LL/128), 256, FFN_SMEM>>>(seq, embed, b1);
    // 2. x = ff @ W2 + b2 + e
    k_ffn<2><<<dim3(2, BB*LL/128), 256, FFN_SMEM>>>(seq, embed, b2);
    // 3. h = LayerNorm(x) in place
    k_ln<<<BB * LL / 8, 256>>>(gamma, beta_ln);
    // 4. chunked delta-rule scan
    k_scan<<<BB * 2, 256, SCAN_SMEM_BYTES>>>();
    // 5-7. readout
    k_read1<<<BB, 256>>>();
    k_read2<<<BB, HH>>>(rp_W, rp_b);
    k_out<<<VV / 128, 256, OUT_SMEM_BYTES>>>(out_W, out_b, out);
}